// round 11
// baseline (speedup 1.0000x reference)
#include <cuda_runtime.h>
#include <cuda_fp16.h>

#define MAXN 100000
#define MAXE 1600000

// ---------------- scratch ----------------
__device__ float d_h[MAXN * 64];
__device__ float d_h2[MAXN * 64];
__device__ __half2 d_hh[2][MAXN * 32];  // pre-scaled {dinv*h[t], dinv*h[t+32]}, dbl-buffered
__device__ __half2 d_g2[MAXN * 32];     // {g[t], g[t+32]} per lane
__device__ float2 d_asp[MAXN * 2];      // {as[hA], as[hA+2]} for hA=0,1
__device__ float2 d_adp[MAXN * 2];
__device__ float d_dinv[MAXN];
__device__ float d_Wc[3 * 64 * 64];

__device__ int d_cnt[2 * MAXN];
__device__ int d_off[2 * MAXN];
__device__ int d_cur[2 * MAXN];
__device__ int d_total[1];
__device__ int d_adj[2 * MAXE];

__device__ __forceinline__ float leaky02(float x) { return x > 0.f ? x : 0.2f * x; }

// ---------------- CSR build ----------------
__global__ void count_kernel(const int* __restrict__ ei, int E, int n) {
    int e = blockIdx.x * blockDim.x + threadIdx.x;
    if (e < E) {
        atomicAdd(&d_cnt[ei[e]], 1);
        atomicAdd(&d_cnt[n + ei[E + e]], 1);
    }
}

__global__ void alloc_kernel(int n2) {
    int i = blockIdx.x * blockDim.x + threadIdx.x;
    if (i < n2) {
        int c = d_cnt[i];
        int o = atomicAdd(&d_total[0], c);
        d_off[i] = o;
        d_cur[i] = o;
    }
}

__global__ void fill_kernel(const int* __restrict__ ei, int E, int n) {
    int e = blockIdx.x * blockDim.x + threadIdx.x;
    if (e < E) {
        int r = ei[e], c = ei[E + e];
        int p = atomicAdd(&d_cur[r], 1);
        d_adj[p] = c;
        int p2 = atomicAdd(&d_cur[n + c], 1);
        d_adj[p2] = r;
    }
}

// ---------------- nodeprep: dinv + emb + n1(layer0) + Wc ----------------
__global__ void __launch_bounds__(256) nodeprep_kernel(
        const float* __restrict__ x, const float* __restrict__ embW,
        const float* __restrict__ embB, const float* __restrict__ gatW,
        const float* __restrict__ attS, const float* __restrict__ attD,
        const float* __restrict__ fusW, const float* __restrict__ e8W,
        int ngrid, int n) {
    if (blockIdx.x >= (unsigned)ngrid) {
        int bid = blockIdx.x - ngrid;
        int gidx = bid * 256 + threadIdx.x;
        if (gidx < 3 * 4096) {
            int layer = gidx >> 12;
            int idx = gidx & 4095;
            int j = idx >> 6, k = idx & 63;
            const float* F = fusW + layer * 64 * 128;
            const float* Ew = e8W + layer * 64 * 64;
            float acc = 0.f;
#pragma unroll
            for (int m = 0; m < 64; m++) acc += F[j * 128 + m] * Ew[m * 64 + k];
            d_Wc[layer * 4096 + j * 64 + k] = acc;
        }
        return;
    }
    __shared__ float We[64 * 65];
    __shared__ float Wg[64 * 65];
    __shared__ float bs[64];
    for (int idx = threadIdx.x; idx < 4096; idx += blockDim.x) {
        int j = idx >> 6, k = idx & 63;
        We[j * 65 + k] = embW[idx];
        Wg[k * 65 + j] = gatW[idx];
    }
    if (threadIdx.x < 64) bs[threadIdx.x] = embB[threadIdx.x];
    __syncthreads();
    int warp = threadIdx.x >> 5, t = threadIdx.x & 31;
    float as0 = attS[t], as1 = attS[t + 32];
    float ad0 = attD[t], ad1 = attD[t + 32];
    for (int node = blockIdx.x * 8 + warp; node < n; node += ngrid * 8) {
        float dg = (float)d_cnt[n + node];
        float dvr = dg > 0.f ? rsqrtf(dg) : 0.f;
        if (t == 0) d_dinv[node] = dvr;
        float in0 = x[node * 64 + t];
        float in1 = x[node * 64 + t + 32];
        float h0 = bs[t], h1 = bs[t + 32];
#pragma unroll
        for (int k = 0; k < 32; k++) {
            float xk = __shfl_sync(0xffffffffu, in0, k);
            h0 += xk * We[t * 65 + k];
            h1 += xk * We[(t + 32) * 65 + k];
        }
#pragma unroll
        for (int k = 0; k < 32; k++) {
            float xk = __shfl_sync(0xffffffffu, in1, k);
            h0 += xk * We[t * 65 + 32 + k];
            h1 += xk * We[(t + 32) * 65 + 32 + k];
        }
        d_h[node * 64 + t] = h0;
        d_h[node * 64 + t + 32] = h1;
        d_hh[0][node * 32 + t] = __floats2half2_rn(dvr * h0, dvr * h1);
        float g0 = 0.f, g1 = 0.f;
#pragma unroll
        for (int k = 0; k < 32; k++) {
            float xk = __shfl_sync(0xffffffffu, h0, k);
            g0 += xk * Wg[t * 65 + k];
            g1 += xk * Wg[(t + 32) * 65 + k];
        }
#pragma unroll
        for (int k = 0; k < 32; k++) {
            float xk = __shfl_sync(0xffffffffu, h1, k);
            g0 += xk * Wg[t * 65 + 32 + k];
            g1 += xk * Wg[(t + 32) * 65 + 32 + k];
        }
        d_g2[node * 32 + t] = __floats2half2_rn(g0, g1);
        float ps0 = g0 * as0, ps1 = g1 * as1;
        float pd0 = g0 * ad0, pd1 = g1 * ad1;
#pragma unroll
        for (int off = 8; off; off >>= 1) {
            ps0 += __shfl_xor_sync(0xffffffffu, ps0, off);
            ps1 += __shfl_xor_sync(0xffffffffu, ps1, off);
            pd0 += __shfl_xor_sync(0xffffffffu, pd0, off);
            pd1 += __shfl_xor_sync(0xffffffffu, pd1, off);
        }
        if ((t & 15) == 0) {
            int hh = t >> 4;
            d_asp[node * 2 + hh] = make_float2(ps0, ps1);
            d_adp[node * 2 + hh] = make_float2(pd0, pd1);
        }
    }
}

// ---------------- N1 (layers 1,2) ----------------
__global__ void __launch_bounds__(256) n1_kernel(
        const float* __restrict__ gatW, const float* __restrict__ attS,
        const float* __restrict__ attD, int layer, int flip, int n) {
    const float* hin = flip ? d_h2 : d_h;
    __shared__ float Wn[64 * 68];
    __shared__ float InB[8][64];
    const float* W = gatW + layer * 4096;
    for (int idx = threadIdx.x; idx < 4096; idx += blockDim.x) {
        int k = idx >> 6, j = idx & 63;
        Wn[j * 68 + k] = W[idx];
    }
    __syncthreads();
    int warp = threadIdx.x >> 5, t = threadIdx.x & 31;
    float as0 = attS[layer * 64 + t], as1 = attS[layer * 64 + t + 32];
    float ad0 = attD[layer * 64 + t], ad1 = attD[layer * 64 + t + 32];
    float* In = InB[warp];
    const float* w0p = &Wn[t * 68];
    const float* w1p = &Wn[(t + 32) * 68];
    for (int node = blockIdx.x * 8 + warp; node < n; node += gridDim.x * 8) {
        In[t] = hin[node * 64 + t];
        In[t + 32] = hin[node * 64 + t + 32];
        __syncwarp();
        float g0 = 0.f, g1 = 0.f;
#pragma unroll
        for (int k4 = 0; k4 < 64; k4 += 4) {
            float4 iv = *reinterpret_cast<const float4*>(&In[k4]);
            float4 w0 = *reinterpret_cast<const float4*>(w0p + k4);
            float4 w1 = *reinterpret_cast<const float4*>(w1p + k4);
            g0 += w0.x * iv.x + w0.y * iv.y + w0.z * iv.z + w0.w * iv.w;
            g1 += w1.x * iv.x + w1.y * iv.y + w1.z * iv.z + w1.w * iv.w;
        }
        __syncwarp();
        d_g2[node * 32 + t] = __floats2half2_rn(g0, g1);
        float ps0 = g0 * as0, ps1 = g1 * as1;
        float pd0 = g0 * ad0, pd1 = g1 * ad1;
#pragma unroll
        for (int off = 8; off; off >>= 1) {
            ps0 += __shfl_xor_sync(0xffffffffu, ps0, off);
            ps1 += __shfl_xor_sync(0xffffffffu, ps1, off);
            pd0 += __shfl_xor_sync(0xffffffffu, pd0, off);
            pd1 += __shfl_xor_sync(0xffffffffu, pd1, off);
        }
        if ((t & 15) == 0) {
            int hh = t >> 4;
            d_asp[node * 2 + hh] = make_float2(ps0, ps1);
            d_adp[node * 2 + hh] = make_float2(pd0, pd1);
        }
    }
}

// ---------------- layer: unrolled gathers + smem-staged float4 pair-GEMV ----------------
__global__ void __launch_bounds__(256) layer_kernel(
        const float* __restrict__ fusW, const float* __restrict__ fusB,
        const float* __restrict__ gatB, const float* __restrict__ lnG,
        const float* __restrict__ lnB, int layer, int flip, int n) {
    const float* hin = flip ? d_h2 : d_h;
    float* hout = flip ? d_h : d_h2;
    const __half2* hhin = d_hh[flip];
    __half2* hhout = d_hh[flip ^ 1];
    __shared__ float Wst[64 * 132];
    __shared__ float InB[8][256];
    __shared__ float fb[64], gb[64], lg[64], lb[64];
    const float* Wc = d_Wc + layer * 4096;
    const float* F = fusW + layer * 64 * 128;
    for (int idx = threadIdx.x; idx < 8192; idx += 256) {
        int j = idx >> 7, k = idx & 127;
        Wst[j * 132 + k] = (k < 64) ? Wc[j * 64 + k] : F[j * 128 + 64 + (k - 64)];
    }
    if (threadIdx.x < 64) {
        fb[threadIdx.x] = fusB[layer * 64 + threadIdx.x];
        gb[threadIdx.x] = gatB[layer * 64 + threadIdx.x];
        lg[threadIdx.x] = lnG[layer * 64 + threadIdx.x];
        lb[threadIdx.x] = lnB[layer * 64 + threadIdx.x];
    }
    __syncthreads();
    int warp = threadIdx.x >> 5, t = threadIdx.x & 31;
    int hA = t >> 4;
    int gw = blockIdx.x * 8 + warp;
    int totw = gridDim.x * 8;
    float* In = InB[warp];
    const float* w0p = &Wst[t * 132];
    const float* w1p = &Wst[(t + 32) * 132];

    for (int nb = gw * 2; nb < n; nb += totw * 2) {
        // ---------- gathers (unrolled for MLP) ----------
#pragma unroll
        for (int q = 0; q < 2; q++) {
            int node = nb + q;
            float a0 = 0.f, a1 = 0.f, xx0 = 0.f, xx1 = 0.f;
            if (node < n) {
                // GAT gather (col-CSR), unroll 2
                float2 adv = d_adp[node * 2 + hA];
                float2 asn = d_asp[node * 2 + hA];
                float eeS0 = __expf(leaky02(asn.x + adv.x));
                float eeS1 = __expf(leaky02(asn.y + adv.y));
                float2 gself = __half22float2(d_g2[node * 32 + t]);
                float w0 = eeS0 * gself.x, w1 = eeS1 * gself.y;
                float s0 = eeS0, s1 = eeS1;
                int beg = d_off[n + node];
                int dc = d_cnt[n + node];
                int i = 0;
                for (; i + 2 <= dc; i += 2) {
                    int sa = __ldg(&d_adj[beg + i]);
                    int sb = __ldg(&d_adj[beg + i + 1]);
                    float2 ga = __half22float2(d_g2[sa * 32 + t]);
                    float2 gbv = __half22float2(d_g2[sb * 32 + t]);
                    float2 aa = __ldg(&d_asp[sa * 2 + hA]);
                    float2 ab = __ldg(&d_asp[sb * 2 + hA]);
                    float ea0 = __expf(leaky02(aa.x + adv.x));
                    float ea1 = __expf(leaky02(aa.y + adv.y));
                    float eb0 = __expf(leaky02(ab.x + adv.x));
                    float eb1 = __expf(leaky02(ab.y + adv.y));
                    w0 += ea0 * ga.x + eb0 * gbv.x;
                    w1 += ea1 * ga.y + eb1 * gbv.y;
                    s0 += ea0 + eb0;
                    s1 += ea1 + eb1;
                }
                if (i < dc) {
                    int sa = __ldg(&d_adj[beg + i]);
                    float2 ga = __half22float2(d_g2[sa * 32 + t]);
                    float2 aa = __ldg(&d_asp[sa * 2 + hA]);
                    float ea0 = __expf(leaky02(aa.x + adv.x));
                    float ea1 = __expf(leaky02(aa.y + adv.y));
                    w0 += ea0 * ga.x;
                    w1 += ea1 * ga.y;
                    s0 += ea0;
                    s1 += ea1;
                }
                xx0 = w0 / s0 + gb[t];
                xx1 = w1 / s1 + gb[t + 32];
                // E8 gather (row-CSR), unroll 4, pre-scaled half2 h
                float e0 = 0.f, e1 = 0.f;
                int beg2 = d_off[node];
                int dr = d_cnt[node];
                int j = 0;
                for (; j + 4 <= dr; j += 4) {
                    int c0 = __ldg(&d_adj[beg2 + j]);
                    int c1 = __ldg(&d_adj[beg2 + j + 1]);
                    int c2 = __ldg(&d_adj[beg2 + j + 2]);
                    int c3 = __ldg(&d_adj[beg2 + j + 3]);
                    float2 h0v = __half22float2(hhin[c0 * 32 + t]);
                    float2 h1v = __half22float2(hhin[c1 * 32 + t]);
                    float2 h2v = __half22float2(hhin[c2 * 32 + t]);
                    float2 h3v = __half22float2(hhin[c3 * 32 + t]);
                    e0 += (h0v.x + h1v.x) + (h2v.x + h3v.x);
                    e1 += (h0v.y + h1v.y) + (h2v.y + h3v.y);
                }
                for (; j < dr; j++) {
                    int c = __ldg(&d_adj[beg2 + j]);
                    float2 hv = __half22float2(hhin[c * 32 + t]);
                    e0 += hv.x;
                    e1 += hv.y;
                }
                float dvr = d_dinv[node];
                a0 = e0 * dvr;
                a1 = e1 * dvr;
            }
            In[q * 128 + t] = a0;
            In[q * 128 + t + 32] = a1;
            In[q * 128 + t + 64] = xx0;
            In[q * 128 + t + 96] = xx1;
        }
        __syncwarp();

        // ---------- pair GEMV ----------
        float accA0 = fb[t], accA1 = fb[t + 32];
        float accB0 = fb[t], accB1 = fb[t + 32];
#pragma unroll 8
        for (int k4 = 0; k4 < 128; k4 += 4) {
            float4 w0 = *reinterpret_cast<const float4*>(w0p + k4);
            float4 w1 = *reinterpret_cast<const float4*>(w1p + k4);
            float4 ia = *reinterpret_cast<const float4*>(&In[k4]);
            float4 ib = *reinterpret_cast<const float4*>(&In[128 + k4]);
            accA0 += w0.x * ia.x + w0.y * ia.y + w0.z * ia.z + w0.w * ia.w;
            accA1 += w1.x * ia.x + w1.y * ia.y + w1.z * ia.z + w1.w * ia.w;
            accB0 += w0.x * ib.x + w0.y * ib.y + w0.z * ib.z + w0.w * ib.w;
            accB1 += w1.x * ib.x + w1.y * ib.y + w1.z * ib.z + w1.w * ib.w;
        }
        __syncwarp();

        // ---------- residual + LN + ReLU + store ----------
#pragma unroll
        for (int q = 0; q < 2; q++) {
            int node = nb + q;
            if (node >= n) break;
            float c0 = (q == 0 ? accA0 : accB0) + hin[node * 64 + t];
            float c1 = (q == 0 ? accA1 : accB1) + hin[node * 64 + t + 32];
            float ssum = c0 + c1;
#pragma unroll
            for (int off = 16; off; off >>= 1) ssum += __shfl_xor_sync(0xffffffffu, ssum, off);
            float mu = ssum * (1.f / 64.f);
            float dd0 = c0 - mu, dd1 = c1 - mu;
            float vs = dd0 * dd0 + dd1 * dd1;
#pragma unroll
            for (int off = 16; off; off >>= 1) vs += __shfl_xor_sync(0xffffffffu, vs, off);
            float rstd = rsqrtf(vs * (1.f / 64.f) + 1e-5f);
            float o0 = fmaxf(dd0 * rstd * lg[t] + lb[t], 0.f);
            float o1 = fmaxf(dd1 * rstd * lg[t + 32] + lb[t + 32], 0.f);
            hout[node * 64 + t] = o0;
            hout[node * 64 + t + 32] = o1;
            float dvr = d_dinv[node];
            hhout[node * 32 + t] = __floats2half2_rn(dvr * o0, dvr * o1);
        }
    }
}

// ---------------- readout ----------------
__global__ void readout_kernel(const float* __restrict__ rW1, const float* __restrict__ rb1,
                               const float* __restrict__ rW2, const float* __restrict__ rb2,
                               float* __restrict__ out, int n) {
    const float* hin = d_h2;
    __shared__ float W1s[32 * 68];
    __shared__ float InB[8][64];
    __shared__ float b1s[32], W2s[32];
    for (int idx = threadIdx.x; idx < 2048; idx += blockDim.x) {
        int m = idx >> 6, k = idx & 63;
        W1s[m * 68 + k] = rW1[idx];
    }
    if (threadIdx.x < 32) {
        b1s[threadIdx.x] = rb1[threadIdx.x];
        W2s[threadIdx.x] = rW2[threadIdx.x];
    }
    __syncthreads();
    float b2 = rb2[0];
    int warp = threadIdx.x >> 5, t = threadIdx.x & 31;
    float* In = InB[warp];
    const float* wp = &W1s[t * 68];
    for (int node = blockIdx.x * 8 + warp; node < n; node += gridDim.x * 8) {
        In[t] = hin[node * 64 + t];
        In[t + 32] = hin[node * 64 + t + 32];
        __syncwarp();
        float acc = b1s[t];
#pragma unroll
        for (int k4 = 0; k4 < 64; k4 += 4) {
            float4 iv = *reinterpret_cast<const float4*>(&In[k4]);
            float4 w = *reinterpret_cast<const float4*>(wp + k4);
            acc += w.x * iv.x + w.y * iv.y + w.z * iv.z + w.w * iv.w;
        }
        __syncwarp();
        acc = fmaxf(acc, 0.f);
        float p = acc * W2s[t];
#pragma unroll
        for (int off = 16; off; off >>= 1) p += __shfl_xor_sync(0xffffffffu, p, off);
        if (t == 0) out[node] = 1.f / (1.f + __expf(-(p + b2)));
    }
}

// ---------------- launch ----------------
extern "C" void kernel_launch(void* const* d_in, const int* in_sizes, int n_in,
                              void* d_out, int out_size) {
    const float* x    = (const float*)d_in[0];
    const int*   ei   = (const int*)d_in[1];
    const float* embW = (const float*)d_in[2];
    const float* embB = (const float*)d_in[3];
    const float* e8W  = (const float*)d_in[4];
    const float* gatW = (const float*)d_in[5];
    const float* attS = (const float*)d_in[6];
    const float* attD = (const float*)d_in[7];
    const float* gatB = (const float*)d_in[8];
    const float* fusW = (const float*)d_in[9];
    const float* fusB = (const float*)d_in[10];
    const float* lnG  = (const float*)d_in[11];
    const float* lnB  = (const float*)d_in[12];
    const float* rW1  = (const float*)d_in[13];
    const float* rb1  = (const float*)d_in[14];
    const float* rW2  = (const float*)d_in[15];
    const float* rb2  = (const float*)d_in[16];
    float* out = (float*)d_out;

    int n = in_sizes[0] / 64;
    int E = in_sizes[1] / 2;
    int n2 = 2 * n;
    int ngrid = 1563;

    void* cnt_addr = nullptr;
    void* tot_addr = nullptr;
    cudaGetSymbolAddress(&cnt_addr, d_cnt);
    cudaGetSymbolAddress(&tot_addr, d_total);
    cudaMemsetAsync(cnt_addr, 0, (size_t)n2 * sizeof(int));
    cudaMemsetAsync(tot_addr, 0, sizeof(int));

    count_kernel<<<(E + 255) / 256, 256>>>(ei, E, n);
    alloc_kernel<<<(n2 + 255) / 256, 256>>>(n2);
    fill_kernel<<<(E + 255) / 256, 256>>>(ei, E, n);
    nodeprep_kernel<<<ngrid + 48, 256>>>(x, embW, embB, gatW, attS, attD, fusW, e8W, ngrid, n);
    layer_kernel<<<ngrid, 256>>>(fusW, fusB, gatB, lnG, lnB, 0, 0, n);
    for (int l = 1; l < 3; l++) {
        int flip = l & 1;
        n1_kernel<<<ngrid, 256>>>(gatW, attS, attD, l, flip, n);
        layer_kernel<<<ngrid, 256>>>(fusW, fusB, gatB, lnG, lnB, l, flip, n);
    }
    readout_kernel<<<ngrid, 256>>>(rW1, rb1, rW2, rb2, out, n);
}

// round 12
// speedup vs baseline: 1.0616x; 1.0616x over previous
#include <cuda_runtime.h>
#include <cuda_fp16.h>

#define MAXN 100000
#define MAXE 1600000

// ---------------- scratch ----------------
__device__ float d_h[MAXN * 64];
__device__ float d_h2[MAXN * 64];
__device__ __half2 d_hh[2][MAXN * 32];  // pre-scaled {dinv*h[t], dinv*h[t+32]}, dbl-buffered
__device__ __half2 d_g2[MAXN * 32];     // {g[t], g[t+32]} per lane
__device__ float2 d_asp[MAXN * 2];      // {as[hA], as[hA+2]} for hA=0,1
__device__ float2 d_adp[MAXN * 2];
__device__ float d_dinv[MAXN];
__device__ float d_Wc[3 * 64 * 64];

__device__ int d_cnt[2 * MAXN];
__device__ int d_off[2 * MAXN];
__device__ int d_cur[2 * MAXN];
__device__ int d_total[1];
__device__ int d_adj[2 * MAXE];

__device__ __forceinline__ float leaky02(float x) { return x > 0.f ? x : 0.2f * x; }

// ---------------- CSR build ----------------
__global__ void count_kernel(const int* __restrict__ ei, int E, int n) {
    int e = blockIdx.x * blockDim.x + threadIdx.x;
    if (e < E) {
        atomicAdd(&d_cnt[ei[e]], 1);
        atomicAdd(&d_cnt[n + ei[E + e]], 1);
    }
}

__global__ void alloc_kernel(int n2) {
    int i = blockIdx.x * blockDim.x + threadIdx.x;
    if (i < n2) {
        int c = d_cnt[i];
        int o = atomicAdd(&d_total[0], c);
        d_off[i] = o;
        d_cur[i] = o;
    }
}

__global__ void fill_kernel(const int* __restrict__ ei, int E, int n) {
    int e = blockIdx.x * blockDim.x + threadIdx.x;
    if (e < E) {
        int r = ei[e], c = ei[E + e];
        int p = atomicAdd(&d_cur[r], 1);
        d_adj[p] = c;
        int p2 = atomicAdd(&d_cur[n + c], 1);
        d_adj[p2] = r;
    }
}

// ---------------- nodeprep: dinv + emb + n1(layer0) + Wc (staged-float4 GEMVs) ----------------
__global__ void __launch_bounds__(256) nodeprep_kernel(
        const float* __restrict__ x, const float* __restrict__ embW,
        const float* __restrict__ embB, const float* __restrict__ gatW,
        const float* __restrict__ attS, const float* __restrict__ attD,
        const float* __restrict__ fusW, const float* __restrict__ e8W,
        int ngrid, int n) {
    if (blockIdx.x >= (unsigned)ngrid) {
        int bid = blockIdx.x - ngrid;
        int gidx = bid * 256 + threadIdx.x;
        if (gidx < 3 * 4096) {
            int layer = gidx >> 12;
            int idx = gidx & 4095;
            int j = idx >> 6, k = idx & 63;
            const float* F = fusW + layer * 64 * 128;
            const float* Ew = e8W + layer * 64 * 64;
            float acc = 0.f;
#pragma unroll
            for (int m = 0; m < 64; m++) acc += F[j * 128 + m] * Ew[m * 64 + k];
            d_Wc[layer * 4096 + j * 64 + k] = acc;
        }
        return;
    }
    __shared__ float We[64 * 68];   // We[j*68+k] = embW[j][k]  (row-major by output j)
    __shared__ float Wg[64 * 68];   // Wg[j*68+k] = gatW[k][j]
    __shared__ float InB[8][64];
    __shared__ float bs[64];
    for (int idx = threadIdx.x; idx < 4096; idx += blockDim.x) {
        int j = idx >> 6, k = idx & 63;
        We[j * 68 + k] = embW[idx];     // embW[j][k], idx = j*64+k
        Wg[k * 68 + j] = gatW[idx];     // gatW[j][k] -> Wg[out k][in j]? careful below
    }
    if (threadIdx.x < 64) bs[threadIdx.x] = embB[threadIdx.x];
    __syncthreads();
    int warp = threadIdx.x >> 5, t = threadIdx.x & 31;
    float as0 = attS[t], as1 = attS[t + 32];
    float ad0 = attD[t], ad1 = attD[t + 32];
    float* In = InB[warp];
    const float* we0 = &We[t * 68];
    const float* we1 = &We[(t + 32) * 68];
    const float* wg0 = &Wg[t * 68];
    const float* wg1 = &Wg[(t + 32) * 68];
    for (int node = blockIdx.x * 8 + warp; node < n; node += ngrid * 8) {
        float dg = (float)d_cnt[n + node];
        float dvr = dg > 0.f ? rsqrtf(dg) : 0.f;
        if (t == 0) d_dinv[node] = dvr;
        // ---- emb: h = x @ embW^T + b (staged float4) ----
        In[t] = x[node * 64 + t];
        In[t + 32] = x[node * 64 + t + 32];
        __syncwarp();
        float h0 = bs[t], h1 = bs[t + 32];
#pragma unroll
        for (int k4 = 0; k4 < 64; k4 += 4) {
            float4 iv = *reinterpret_cast<const float4*>(&In[k4]);
            float4 w0 = *reinterpret_cast<const float4*>(we0 + k4);
            float4 w1 = *reinterpret_cast<const float4*>(we1 + k4);
            h0 += w0.x * iv.x + w0.y * iv.y + w0.z * iv.z + w0.w * iv.w;
            h1 += w1.x * iv.x + w1.y * iv.y + w1.z * iv.z + w1.w * iv.w;
        }
        __syncwarp();
        d_h[node * 64 + t] = h0;
        d_h[node * 64 + t + 32] = h1;
        d_hh[0][node * 32 + t] = __floats2half2_rn(dvr * h0, dvr * h1);
        // ---- gat layer0: g = h @ gatW (staged float4) ----
        In[t] = h0;
        In[t + 32] = h1;
        __syncwarp();
        float g0 = 0.f, g1 = 0.f;
#pragma unroll
        for (int k4 = 0; k4 < 64; k4 += 4) {
            float4 iv = *reinterpret_cast<const float4*>(&In[k4]);
            float4 w0 = *reinterpret_cast<const float4*>(wg0 + k4);
            float4 w1 = *reinterpret_cast<const float4*>(wg1 + k4);
            g0 += w0.x * iv.x + w0.y * iv.y + w0.z * iv.z + w0.w * iv.w;
            g1 += w1.x * iv.x + w1.y * iv.y + w1.z * iv.z + w1.w * iv.w;
        }
        __syncwarp();
        d_g2[node * 32 + t] = __floats2half2_rn(g0, g1);
        float ps0 = g0 * as0, ps1 = g1 * as1;
        float pd0 = g0 * ad0, pd1 = g1 * ad1;
#pragma unroll
        for (int off = 8; off; off >>= 1) {
            ps0 += __shfl_xor_sync(0xffffffffu, ps0, off);
            ps1 += __shfl_xor_sync(0xffffffffu, ps1, off);
            pd0 += __shfl_xor_sync(0xffffffffu, pd0, off);
            pd1 += __shfl_xor_sync(0xffffffffu, pd1, off);
        }
        if ((t & 15) == 0) {
            int hh = t >> 4;
            d_asp[node * 2 + hh] = make_float2(ps0, ps1);
            d_adp[node * 2 + hh] = make_float2(pd0, pd1);
        }
    }
}

// ---------------- N1 (layers 1,2) ----------------
__global__ void __launch_bounds__(256) n1_kernel(
        const float* __restrict__ gatW, const float* __restrict__ attS,
        const float* __restrict__ attD, int layer, int flip, int n) {
    const float* hin = flip ? d_h2 : d_h;
    __shared__ float Wn[64 * 68];
    __shared__ float InB[8][64];
    const float* W = gatW + layer * 4096;
    for (int idx = threadIdx.x; idx < 4096; idx += blockDim.x) {
        int k = idx >> 6, j = idx & 63;
        Wn[j * 68 + k] = W[idx];
    }
    __syncthreads();
    int warp = threadIdx.x >> 5, t = threadIdx.x & 31;
    float as0 = attS[layer * 64 + t], as1 = attS[layer * 64 + t + 32];
    float ad0 = attD[layer * 64 + t], ad1 = attD[layer * 64 + t + 32];
    float* In = InB[warp];
    const float* w0p = &Wn[t * 68];
    const float* w1p = &Wn[(t + 32) * 68];
    for (int node = blockIdx.x * 8 + warp; node < n; node += gridDim.x * 8) {
        In[t] = hin[node * 64 + t];
        In[t + 32] = hin[node * 64 + t + 32];
        __syncwarp();
        float g0 = 0.f, g1 = 0.f;
#pragma unroll
        for (int k4 = 0; k4 < 64; k4 += 4) {
            float4 iv = *reinterpret_cast<const float4*>(&In[k4]);
            float4 w0 = *reinterpret_cast<const float4*>(w0p + k4);
            float4 w1 = *reinterpret_cast<const float4*>(w1p + k4);
            g0 += w0.x * iv.x + w0.y * iv.y + w0.z * iv.z + w0.w * iv.w;
            g1 += w1.x * iv.x + w1.y * iv.y + w1.z * iv.z + w1.w * iv.w;
        }
        __syncwarp();
        d_g2[node * 32 + t] = __floats2half2_rn(g0, g1);
        float ps0 = g0 * as0, ps1 = g1 * as1;
        float pd0 = g0 * ad0, pd1 = g1 * ad1;
#pragma unroll
        for (int off = 8; off; off >>= 1) {
            ps0 += __shfl_xor_sync(0xffffffffu, ps0, off);
            ps1 += __shfl_xor_sync(0xffffffffu, ps1, off);
            pd0 += __shfl_xor_sync(0xffffffffu, pd0, off);
            pd1 += __shfl_xor_sync(0xffffffffu, pd1, off);
        }
        if ((t & 15) == 0) {
            int hh = t >> 4;
            d_asp[node * 2 + hh] = make_float2(ps0, ps1);
            d_adp[node * 2 + hh] = make_float2(pd0, pd1);
        }
    }
}

// ---------------- layer: R10 gathers + smem-staged float4 pair-GEMV ----------------
__global__ void __launch_bounds__(256) layer_kernel(
        const float* __restrict__ fusW, const float* __restrict__ fusB,
        const float* __restrict__ gatB, const float* __restrict__ lnG,
        const float* __restrict__ lnB, int layer, int flip, int n) {
    const float* hin = flip ? d_h2 : d_h;
    float* hout = flip ? d_h : d_h2;
    const __half2* hhin = d_hh[flip];
    __half2* hhout = d_hh[flip ^ 1];
    __shared__ float Wst[64 * 132];
    __shared__ float InB[8][256];
    __shared__ float fb[64], gb[64], lg[64], lb[64];
    const float* Wc = d_Wc + layer * 4096;
    const float* F = fusW + layer * 64 * 128;
    for (int idx = threadIdx.x; idx < 8192; idx += 256) {
        int j = idx >> 7, k = idx & 127;
        Wst[j * 132 + k] = (k < 64) ? Wc[j * 64 + k] : F[j * 128 + 64 + (k - 64)];
    }
    if (threadIdx.x < 64) {
        fb[threadIdx.x] = fusB[layer * 64 + threadIdx.x];
        gb[threadIdx.x] = gatB[layer * 64 + threadIdx.x];
        lg[threadIdx.x] = lnG[layer * 64 + threadIdx.x];
        lb[threadIdx.x] = lnB[layer * 64 + threadIdx.x];
    }
    __syncthreads();
    int warp = threadIdx.x >> 5, t = threadIdx.x & 31;
    int hA = t >> 4;
    int gw = blockIdx.x * 8 + warp;
    int totw = gridDim.x * 8;
    float* In = InB[warp];
    const float* w0p = &Wst[t * 132];
    const float* w1p = &Wst[(t + 32) * 132];

    for (int nb = gw * 2; nb < n; nb += totw * 2) {
        // ---------- gathers (R10 form) ----------
#pragma unroll
        for (int q = 0; q < 2; q++) {
            int node = nb + q;
            float a0 = 0.f, a1 = 0.f, xx0 = 0.f, xx1 = 0.f;
            if (node < n) {
                float2 adv = d_adp[node * 2 + hA];
                float2 asn = d_asp[node * 2 + hA];
                float eeS0 = __expf(leaky02(asn.x + adv.x));
                float eeS1 = __expf(leaky02(asn.y + adv.y));
                float2 gself = __half22float2(d_g2[node * 32 + t]);
                float w0 = eeS0 * gself.x, w1 = eeS1 * gself.y;
                float s0 = eeS0, s1 = eeS1;
                int beg = d_off[n + node];
                int dc = d_cnt[n + node];
                for (int i = 0; i < dc; i++) {
                    int src = __ldg(&d_adj[beg + i]);
                    float2 gv = __half22float2(d_g2[src * 32 + t]);
                    float2 asv = __ldg(&d_asp[src * 2 + hA]);
                    float ee0 = __expf(leaky02(asv.x + adv.x));
                    float ee1 = __expf(leaky02(asv.y + adv.y));
                    w0 += ee0 * gv.x;
                    w1 += ee1 * gv.y;
                    s0 += ee0;
                    s1 += ee1;
                }
                xx0 = w0 / s0 + gb[t];
                xx1 = w1 / s1 + gb[t + 32];
                float e0 = 0.f, e1 = 0.f;
                int beg2 = d_off[node];
                int dr = d_cnt[node];
                for (int i = 0; i < dr; i++) {
                    int c = __ldg(&d_adj[beg2 + i]);
                    float2 hv = __half22float2(hhin[c * 32 + t]);
                    e0 += hv.x;
                    e1 += hv.y;
                }
                float dvr = d_dinv[node];
                a0 = e0 * dvr;
                a1 = e1 * dvr;
            }
            In[q * 128 + t] = a0;
            In[q * 128 + t + 32] = a1;
            In[q * 128 + t + 64] = xx0;
            In[q * 128 + t + 96] = xx1;
        }
        __syncwarp();

        // ---------- pair GEMV ----------
        float accA0 = fb[t], accA1 = fb[t + 32];
        float accB0 = fb[t], accB1 = fb[t + 32];
#pragma unroll 8
        for (int k4 = 0; k4 < 128; k4 += 4) {
            float4 w0 = *reinterpret_cast<const float4*>(w0p + k4);
            float4 w1 = *reinterpret_cast<const float4*>(w1p + k4);
            float4 ia = *reinterpret_cast<const float4*>(&In[k4]);
            float4 ib = *reinterpret_cast<const float4*>(&In[128 + k4]);
            accA0 += w0.x * ia.x + w0.y * ia.y + w0.z * ia.z + w0.w * ia.w;
            accA1 += w1.x * ia.x + w1.y * ia.y + w1.z * ia.z + w1.w * ia.w;
            accB0 += w0.x * ib.x + w0.y * ib.y + w0.z * ib.z + w0.w * ib.w;
            accB1 += w1.x * ib.x + w1.y * ib.y + w1.z * ib.z + w1.w * ib.w;
        }
        __syncwarp();

        // ---------- residual + LN + ReLU + store ----------
#pragma unroll
        for (int q = 0; q < 2; q++) {
            int node = nb + q;
            if (node >= n) break;
            float c0 = (q == 0 ? accA0 : accB0) + hin[node * 64 + t];
            float c1 = (q == 0 ? accA1 : accB1) + hin[node * 64 + t + 32];
            float ssum = c0 + c1;
#pragma unroll
            for (int off = 16; off; off >>= 1) ssum += __shfl_xor_sync(0xffffffffu, ssum, off);
            float mu = ssum * (1.f / 64.f);
            float dd0 = c0 - mu, dd1 = c1 - mu;
            float vs = dd0 * dd0 + dd1 * dd1;
#pragma unroll
            for (int off = 16; off; off >>= 1) vs += __shfl_xor_sync(0xffffffffu, vs, off);
            float rstd = rsqrtf(vs * (1.f / 64.f) + 1e-5f);
            float o0 = fmaxf(dd0 * rstd * lg[t] + lb[t], 0.f);
            float o1 = fmaxf(dd1 * rstd * lg[t + 32] + lb[t + 32], 0.f);
            hout[node * 64 + t] = o0;
            hout[node * 64 + t + 32] = o1;
            float dvr = d_dinv[node];
            hhout[node * 32 + t] = __floats2half2_rn(dvr * o0, dvr * o1);
        }
    }
}

// ---------------- readout ----------------
__global__ void readout_kernel(const float* __restrict__ rW1, const float* __restrict__ rb1,
                               const float* __restrict__ rW2, const float* __restrict__ rb2,
                               float* __restrict__ out, int n) {
    const float* hin = d_h2;
    __shared__ float W1s[32 * 68];
    __shared__ float InB[8][64];
    __shared__ float b1s[32], W2s[32];
    for (int idx = threadIdx.x; idx < 2048; idx += blockDim.x) {
        int m = idx >> 6, k = idx & 63;
        W1s[m * 68 + k] = rW1[idx];
    }
    if (threadIdx.x < 32) {
        b1s[threadIdx.x] = rb1[threadIdx.x];
        W2s[threadIdx.x] = rW2[threadIdx.x];
    }
    __syncthreads();
    float b2 = rb2[0];
    int warp = threadIdx.x >> 5, t = threadIdx.x & 31;
    float* In = InB[warp];
    const float* wp = &W1s[t * 68];
    for (int node = blockIdx.x * 8 + warp; node < n; node += gridDim.x * 8) {
        In[t] = hin[node * 64 + t];
        In[t + 32] = hin[node * 64 + t + 32];
        __syncwarp();
        float acc = b1s[t];
#pragma unroll
        for (int k4 = 0; k4 < 64; k4 += 4) {
            float4 iv = *reinterpret_cast<const float4*>(&In[k4]);
            float4 w = *reinterpret_cast<const float4*>(wp + k4);
            acc += w.x * iv.x + w.y * iv.y + w.z * iv.z + w.w * iv.w;
        }
        __syncwarp();
        acc = fmaxf(acc, 0.f);
        float p = acc * W2s[t];
#pragma unroll
        for (int off = 16; off; off >>= 1) p += __shfl_xor_sync(0xffffffffu, p, off);
        if (t == 0) out[node] = 1.f / (1.f + __expf(-(p + b2)));
    }
}

// ---------------- launch ----------------
extern "C" void kernel_launch(void* const* d_in, const int* in_sizes, int n_in,
                              void* d_out, int out_size) {
    const float* x    = (const float*)d_in[0];
    const int*   ei   = (const int*)d_in[1];
    const float* embW = (const float*)d_in[2];
    const float* embB = (const float*)d_in[3];
    const float* e8W  = (const float*)d_in[4];
    const float* gatW = (const float*)d_in[5];
    const float* attS = (const float*)d_in[6];
    const float* attD = (const float*)d_in[7];
    const float* gatB = (const float*)d_in[8];
    const float* fusW = (const float*)d_in[9];
    const float* fusB = (const float*)d_in[10];
    const float* lnG  = (const float*)d_in[11];
    const float* lnB  = (const float*)d_in[12];
    const float* rW1  = (const float*)d_in[13];
    const float* rb1  = (const float*)d_in[14];
    const float* rW2  = (const float*)d_in[15];
    const float* rb2  = (const float*)d_in[16];
    float* out = (float*)d_out;

    int n = in_sizes[0] / 64;
    int E = in_sizes[1] / 2;
    int n2 = 2 * n;
    int ngrid = 1563;

    void* cnt_addr = nullptr;
    void* tot_addr = nullptr;
    cudaGetSymbolAddress(&cnt_addr, d_cnt);
    cudaGetSymbolAddress(&tot_addr, d_total);
    cudaMemsetAsync(cnt_addr, 0, (size_t)n2 * sizeof(int));
    cudaMemsetAsync(tot_addr, 0, sizeof(int));

    count_kernel<<<(E + 255) / 256, 256>>>(ei, E, n);
    alloc_kernel<<<(n2 + 255) / 256, 256>>>(n2);
    fill_kernel<<<(E + 255) / 256, 256>>>(ei, E, n);
    nodeprep_kernel<<<ngrid + 48, 256>>>(x, embW, embB, gatW, attS, attD, fusW, e8W, ngrid, n);
    layer_kernel<<<ngrid, 256>>>(fusW, fusB, gatB, lnG, lnB, 0, 0, n);
    for (int l = 1; l < 3; l++) {
        int flip = l & 1;
        n1_kernel<<<ngrid, 256>>>(gatW, attS, attD, l, flip, n);
        layer_kernel<<<ngrid, 256>>>(fusW, fusB, gatB, lnG, lnB, l, flip, n);
    }
    readout_kernel<<<ngrid, 256>>>(rW1, rb1, rW2, rb2, out, n);
}

// round 13
// speedup vs baseline: 1.1724x; 1.1044x over previous
#include <cuda_runtime.h>
#include <cuda_fp16.h>

#define MAXN 100000
#define MAXE 1600000

// ---------------- scratch ----------------
__device__ float d_h[MAXN * 64];
__device__ float d_h2[MAXN * 64];
__device__ __half2 d_hh[2][MAXN * 32];  // pre-scaled {dinv*h[t], dinv*h[t+32]}, dbl-buffered
__device__ __half2 d_g2[MAXN * 32];     // {g[t], g[t+32]} per lane
__device__ float2 d_asp[MAXN * 2];      // {as[hA], as[hA+2]} for hA=0,1
__device__ float2 d_adp[MAXN * 2];
__device__ float d_dinv[MAXN];
__device__ float d_Wc[3 * 64 * 64];

__device__ int d_cnt[2 * MAXN];
__device__ int d_off[2 * MAXN];
__device__ int d_cur[2 * MAXN];
__device__ int d_total[1];
__device__ int d_adj[2 * MAXE];

__device__ __forceinline__ float leaky02(float x) { return x > 0.f ? x : 0.2f * x; }

// ---------------- CSR build ----------------
__global__ void count_kernel(const int* __restrict__ ei, int E, int n) {
    int e = blockIdx.x * blockDim.x + threadIdx.x;
    if (e < E) {
        atomicAdd(&d_cnt[ei[e]], 1);
        atomicAdd(&d_cnt[n + ei[E + e]], 1);
    }
}

__global__ void alloc_kernel(int n2) {
    int i = blockIdx.x * blockDim.x + threadIdx.x;
    if (i < n2) {
        int c = d_cnt[i];
        int o = atomicAdd(&d_total[0], c);
        d_off[i] = o;
        d_cur[i] = o;
    }
}

__global__ void fill_kernel(const int* __restrict__ ei, int E, int n) {
    int e = blockIdx.x * blockDim.x + threadIdx.x;
    if (e < E) {
        int r = ei[e], c = ei[E + e];
        int p = atomicAdd(&d_cur[r], 1);
        d_adj[p] = c;
        int p2 = atomicAdd(&d_cur[n + c], 1);
        d_adj[p2] = r;
    }
}

// ---------------- nodeprep: dinv + emb + n1(layer0) + Wc (pair-GEMVs) ----------------
__global__ void __launch_bounds__(256) nodeprep_kernel(
        const float* __restrict__ x, const float* __restrict__ embW,
        const float* __restrict__ embB, const float* __restrict__ gatW,
        const float* __restrict__ attS, const float* __restrict__ attD,
        const float* __restrict__ fusW, const float* __restrict__ e8W,
        int ngrid, int n) {
    if (blockIdx.x >= (unsigned)ngrid) {
        int bid = blockIdx.x - ngrid;
        int gidx = bid * 256 + threadIdx.x;
        if (gidx < 3 * 4096) {
            int layer = gidx >> 12;
            int idx = gidx & 4095;
            int j = idx >> 6, k = idx & 63;
            const float* F = fusW + layer * 64 * 128;
            const float* Ew = e8W + layer * 64 * 64;
            float acc = 0.f;
#pragma unroll
            for (int m = 0; m < 64; m++) acc += F[j * 128 + m] * Ew[m * 64 + k];
            d_Wc[layer * 4096 + j * 64 + k] = acc;
        }
        return;
    }
    __shared__ float We[64 * 68];   // We[j*68+k] = embW[j][k]
    __shared__ float Wg[64 * 68];   // Wg[j*68+k] = gatW[k][j]
    __shared__ float InB[8][128];   // per-warp: [0,64)=node A, [64,128)=node B
    __shared__ float bs[64];
    for (int idx = threadIdx.x; idx < 4096; idx += blockDim.x) {
        int j = idx >> 6, k = idx & 63;
        We[j * 68 + k] = embW[idx];
        Wg[k * 68 + j] = gatW[idx];
    }
    if (threadIdx.x < 64) bs[threadIdx.x] = embB[threadIdx.x];
    __syncthreads();
    int warp = threadIdx.x >> 5, t = threadIdx.x & 31;
    float as0 = attS[t], as1 = attS[t + 32];
    float ad0 = attD[t], ad1 = attD[t + 32];
    float* In = InB[warp];
    const float* we0 = &We[t * 68];
    const float* we1 = &We[(t + 32) * 68];
    const float* wg0 = &Wg[t * 68];
    const float* wg1 = &Wg[(t + 32) * 68];
    int gw = blockIdx.x * 8 + warp;
    int totw = ngrid * 8;
    for (int nb = gw * 2; nb < n; nb += totw * 2) {
        int nodeA = nb, nodeB = nb + 1;
        bool hasB = nodeB < n;
        // stage x for both nodes
        In[t] = x[nodeA * 64 + t];
        In[t + 32] = x[nodeA * 64 + t + 32];
        In[64 + t] = hasB ? x[nodeB * 64 + t] : 0.f;
        In[96 + t] = hasB ? x[nodeB * 64 + t + 32] : 0.f;
        __syncwarp();
        // ---- emb pair-GEMV ----
        float hA0 = bs[t], hA1 = bs[t + 32];
        float hB0 = bs[t], hB1 = bs[t + 32];
#pragma unroll
        for (int k4 = 0; k4 < 64; k4 += 4) {
            float4 w0 = *reinterpret_cast<const float4*>(we0 + k4);
            float4 w1 = *reinterpret_cast<const float4*>(we1 + k4);
            float4 ia = *reinterpret_cast<const float4*>(&In[k4]);
            float4 ib = *reinterpret_cast<const float4*>(&In[64 + k4]);
            hA0 += w0.x * ia.x + w0.y * ia.y + w0.z * ia.z + w0.w * ia.w;
            hA1 += w1.x * ia.x + w1.y * ia.y + w1.z * ia.z + w1.w * ia.w;
            hB0 += w0.x * ib.x + w0.y * ib.y + w0.z * ib.z + w0.w * ib.w;
            hB1 += w1.x * ib.x + w1.y * ib.y + w1.z * ib.z + w1.w * ib.w;
        }
        __syncwarp();
        {
            float dgA = (float)d_cnt[n + nodeA];
            float dvrA = dgA > 0.f ? rsqrtf(dgA) : 0.f;
            if (t == 0) d_dinv[nodeA] = dvrA;
            d_h[nodeA * 64 + t] = hA0;
            d_h[nodeA * 64 + t + 32] = hA1;
            d_hh[0][nodeA * 32 + t] = __floats2half2_rn(dvrA * hA0, dvrA * hA1);
        }
        if (hasB) {
            float dgB = (float)d_cnt[n + nodeB];
            float dvrB = dgB > 0.f ? rsqrtf(dgB) : 0.f;
            if (t == 0) d_dinv[nodeB] = dvrB;
            d_h[nodeB * 64 + t] = hB0;
            d_h[nodeB * 64 + t + 32] = hB1;
            d_hh[0][nodeB * 32 + t] = __floats2half2_rn(dvrB * hB0, dvrB * hB1);
        }
        // stage h for both nodes
        In[t] = hA0;
        In[t + 32] = hA1;
        In[64 + t] = hB0;
        In[96 + t] = hB1;
        __syncwarp();
        // ---- gat layer0 pair-GEMV ----
        float gA0 = 0.f, gA1 = 0.f, gB0 = 0.f, gB1 = 0.f;
#pragma unroll
        for (int k4 = 0; k4 < 64; k4 += 4) {
            float4 w0 = *reinterpret_cast<const float4*>(wg0 + k4);
            float4 w1 = *reinterpret_cast<const float4*>(wg1 + k4);
            float4 ia = *reinterpret_cast<const float4*>(&In[k4]);
            float4 ib = *reinterpret_cast<const float4*>(&In[64 + k4]);
            gA0 += w0.x * ia.x + w0.y * ia.y + w0.z * ia.z + w0.w * ia.w;
            gA1 += w1.x * ia.x + w1.y * ia.y + w1.z * ia.z + w1.w * ia.w;
            gB0 += w0.x * ib.x + w0.y * ib.y + w0.z * ib.z + w0.w * ib.w;
            gB1 += w1.x * ib.x + w1.y * ib.y + w1.z * ib.z + w1.w * ib.w;
        }
        __syncwarp();
#pragma unroll
        for (int q = 0; q < 2; q++) {
            int node = nb + q;
            if (node >= n) break;
            float g0 = q ? gB0 : gA0;
            float g1 = q ? gB1 : gA1;
            d_g2[node * 32 + t] = __floats2half2_rn(g0, g1);
            float ps0 = g0 * as0, ps1 = g1 * as1;
            float pd0 = g0 * ad0, pd1 = g1 * ad1;
#pragma unroll
            for (int off = 8; off; off >>= 1) {
                ps0 += __shfl_xor_sync(0xffffffffu, ps0, off);
                ps1 += __shfl_xor_sync(0xffffffffu, ps1, off);
                pd0 += __shfl_xor_sync(0xffffffffu, pd0, off);
                pd1 += __shfl_xor_sync(0xffffffffu, pd1, off);
            }
            if ((t & 15) == 0) {
                int hh = t >> 4;
                d_asp[node * 2 + hh] = make_float2(ps0, ps1);
                d_adp[node * 2 + hh] = make_float2(pd0, pd1);
            }
        }
    }
}

// ---------------- N1 (layers 1,2): pair-GEMV ----------------
__global__ void __launch_bounds__(256) n1_kernel(
        const float* __restrict__ gatW, const float* __restrict__ attS,
        const float* __restrict__ attD, int layer, int flip, int n) {
    const float* hin = flip ? d_h2 : d_h;
    __shared__ float Wn[64 * 68];
    __shared__ float InB[8][128];
    const float* W = gatW + layer * 4096;
    for (int idx = threadIdx.x; idx < 4096; idx += blockDim.x) {
        int k = idx >> 6, j = idx & 63;
        Wn[j * 68 + k] = W[idx];
    }
    __syncthreads();
    int warp = threadIdx.x >> 5, t = threadIdx.x & 31;
    float as0 = attS[layer * 64 + t], as1 = attS[layer * 64 + t + 32];
    float ad0 = attD[layer * 64 + t], ad1 = attD[layer * 64 + t + 32];
    float* In = InB[warp];
    const float* w0p = &Wn[t * 68];
    const float* w1p = &Wn[(t + 32) * 68];
    int gw = blockIdx.x * 8 + warp;
    int totw = gridDim.x * 8;
    for (int nb = gw * 2; nb < n; nb += totw * 2) {
        int nodeA = nb, nodeB = nb + 1;
        bool hasB = nodeB < n;
        In[t] = hin[nodeA * 64 + t];
        In[t + 32] = hin[nodeA * 64 + t + 32];
        In[64 + t] = hasB ? hin[nodeB * 64 + t] : 0.f;
        In[96 + t] = hasB ? hin[nodeB * 64 + t + 32] : 0.f;
        __syncwarp();
        float gA0 = 0.f, gA1 = 0.f, gB0 = 0.f, gB1 = 0.f;
#pragma unroll
        for (int k4 = 0; k4 < 64; k4 += 4) {
            float4 w0 = *reinterpret_cast<const float4*>(w0p + k4);
            float4 w1 = *reinterpret_cast<const float4*>(w1p + k4);
            float4 ia = *reinterpret_cast<const float4*>(&In[k4]);
            float4 ib = *reinterpret_cast<const float4*>(&In[64 + k4]);
            gA0 += w0.x * ia.x + w0.y * ia.y + w0.z * ia.z + w0.w * ia.w;
            gA1 += w1.x * ia.x + w1.y * ia.y + w1.z * ia.z + w1.w * ia.w;
            gB0 += w0.x * ib.x + w0.y * ib.y + w0.z * ib.z + w0.w * ib.w;
            gB1 += w1.x * ib.x + w1.y * ib.y + w1.z * ib.z + w1.w * ib.w;
        }
        __syncwarp();
#pragma unroll
        for (int q = 0; q < 2; q++) {
            int node = nb + q;
            if (node >= n) break;
            float g0 = q ? gB0 : gA0;
            float g1 = q ? gB1 : gA1;
            d_g2[node * 32 + t] = __floats2half2_rn(g0, g1);
            float ps0 = g0 * as0, ps1 = g1 * as1;
            float pd0 = g0 * ad0, pd1 = g1 * ad1;
#pragma unroll
            for (int off = 8; off; off >>= 1) {
                ps0 += __shfl_xor_sync(0xffffffffu, ps0, off);
                ps1 += __shfl_xor_sync(0xffffffffu, ps1, off);
                pd0 += __shfl_xor_sync(0xffffffffu, pd0, off);
                pd1 += __shfl_xor_sync(0xffffffffu, pd1, off);
            }
            if ((t & 15) == 0) {
                int hh = t >> 4;
                d_asp[node * 2 + hh] = make_float2(ps0, ps1);
                d_adp[node * 2 + hh] = make_float2(pd0, pd1);
            }
        }
    }
}

// ---------------- layer: R10 gathers + smem-staged float4 pair-GEMV ----------------
__global__ void __launch_bounds__(256) layer_kernel(
        const float* __restrict__ fusW, const float* __restrict__ fusB,
        const float* __restrict__ gatB, const float* __restrict__ lnG,
        const float* __restrict__ lnB, int layer, int flip, int n) {
    const float* hin = flip ? d_h2 : d_h;
    float* hout = flip ? d_h : d_h2;
    const __half2* hhin = d_hh[flip];
    __half2* hhout = d_hh[flip ^ 1];
    __shared__ float Wst[64 * 132];
    __shared__ float InB[8][256];
    __shared__ float fb[64], gb[64], lg[64], lb[64];
    const float* Wc = d_Wc + layer * 4096;
    const float* F = fusW + layer * 64 * 128;
    for (int idx = threadIdx.x; idx < 8192; idx += 256) {
        int j = idx >> 7, k = idx & 127;
        Wst[j * 132 + k] = (k < 64) ? Wc[j * 64 + k] : F[j * 128 + 64 + (k - 64)];
    }
    if (threadIdx.x < 64) {
        fb[threadIdx.x] = fusB[layer * 64 + threadIdx.x];
        gb[threadIdx.x] = gatB[layer * 64 + threadIdx.x];
        lg[threadIdx.x] = lnG[layer * 64 + threadIdx.x];
        lb[threadIdx.x] = lnB[layer * 64 + threadIdx.x];
    }
    __syncthreads();
    int warp = threadIdx.x >> 5, t = threadIdx.x & 31;
    int hA = t >> 4;
    int gw = blockIdx.x * 8 + warp;
    int totw = gridDim.x * 8;
    float* In = InB[warp];
    const float* w0p = &Wst[t * 132];
    const float* w1p = &Wst[(t + 32) * 132];

    for (int nb = gw * 2; nb < n; nb += totw * 2) {
#pragma unroll
        for (int q = 0; q < 2; q++) {
            int node = nb + q;
            float a0 = 0.f, a1 = 0.f, xx0 = 0.f, xx1 = 0.f;
            if (node < n) {
                float2 adv = d_adp[node * 2 + hA];
                float2 asn = d_asp[node * 2 + hA];
                float eeS0 = __expf(leaky02(asn.x + adv.x));
                float eeS1 = __expf(leaky02(asn.y + adv.y));
                float2 gself = __half22float2(d_g2[node * 32 + t]);
                float w0 = eeS0 * gself.x, w1 = eeS1 * gself.y;
                float s0 = eeS0, s1 = eeS1;
                int beg = d_off[n + node];
                int dc = d_cnt[n + node];
                for (int i = 0; i < dc; i++) {
                    int src = __ldg(&d_adj[beg + i]);
                    float2 gv = __half22float2(d_g2[src * 32 + t]);
                    float2 asv = __ldg(&d_asp[src * 2 + hA]);
                    float ee0 = __expf(leaky02(asv.x + adv.x));
                    float ee1 = __expf(leaky02(asv.y + adv.y));
                    w0 += ee0 * gv.x;
                    w1 += ee1 * gv.y;
                    s0 += ee0;
                    s1 += ee1;
                }
                xx0 = w0 / s0 + gb[t];
                xx1 = w1 / s1 + gb[t + 32];
                float e0 = 0.f, e1 = 0.f;
                int beg2 = d_off[node];
                int dr = d_cnt[node];
                for (int i = 0; i < dr; i++) {
                    int c = __ldg(&d_adj[beg2 + i]);
                    float2 hv = __half22float2(hhin[c * 32 + t]);
                    e0 += hv.x;
                    e1 += hv.y;
                }
                float dvr = d_dinv[node];
                a0 = e0 * dvr;
                a1 = e1 * dvr;
            }
            In[q * 128 + t] = a0;
            In[q * 128 + t + 32] = a1;
            In[q * 128 + t + 64] = xx0;
            In[q * 128 + t + 96] = xx1;
        }
        __syncwarp();

        float accA0 = fb[t], accA1 = fb[t + 32];
        float accB0 = fb[t], accB1 = fb[t + 32];
#pragma unroll 8
        for (int k4 = 0; k4 < 128; k4 += 4) {
            float4 w0 = *reinterpret_cast<const float4*>(w0p + k4);
            float4 w1 = *reinterpret_cast<const float4*>(w1p + k4);
            float4 ia = *reinterpret_cast<const float4*>(&In[k4]);
            float4 ib = *reinterpret_cast<const float4*>(&In[128 + k4]);
            accA0 += w0.x * ia.x + w0.y * ia.y + w0.z * ia.z + w0.w * ia.w;
            accA1 += w1.x * ia.x + w1.y * ia.y + w1.z * ia.z + w1.w * ia.w;
            accB0 += w0.x * ib.x + w0.y * ib.y + w0.z * ib.z + w0.w * ib.w;
            accB1 += w1.x * ib.x + w1.y * ib.y + w1.z * ib.z + w1.w * ib.w;
        }
        __syncwarp();

#pragma unroll
        for (int q = 0; q < 2; q++) {
            int node = nb + q;
            if (node >= n) break;
            float c0 = (q == 0 ? accA0 : accB0) + hin[node * 64 + t];
            float c1 = (q == 0 ? accA1 : accB1) + hin[node * 64 + t + 32];
            float ssum = c0 + c1;
#pragma unroll
            for (int off = 16; off; off >>= 1) ssum += __shfl_xor_sync(0xffffffffu, ssum, off);
            float mu = ssum * (1.f / 64.f);
            float dd0 = c0 - mu, dd1 = c1 - mu;
            float vs = dd0 * dd0 + dd1 * dd1;
#pragma unroll
            for (int off = 16; off; off >>= 1) vs += __shfl_xor_sync(0xffffffffu, vs, off);
            float rstd = rsqrtf(vs * (1.f / 64.f) + 1e-5f);
            float o0 = fmaxf(dd0 * rstd * lg[t] + lb[t], 0.f);
            float o1 = fmaxf(dd1 * rstd * lg[t + 32] + lb[t + 32], 0.f);
            hout[node * 64 + t] = o0;
            hout[node * 64 + t + 32] = o1;
            float dvr = d_dinv[node];
            hhout[node * 32 + t] = __floats2half2_rn(dvr * o0, dvr * o1);
        }
    }
}

// ---------------- readout ----------------
__global__ void readout_kernel(const float* __restrict__ rW1, const float* __restrict__ rb1,
                               const float* __restrict__ rW2, const float* __restrict__ rb2,
                               float* __restrict__ out, int n) {
    const float* hin = d_h2;
    __shared__ float W1s[32 * 68];
    __shared__ float InB[8][64];
    __shared__ float b1s[32], W2s[32];
    for (int idx = threadIdx.x; idx < 2048; idx += blockDim.x) {
        int m = idx >> 6, k = idx & 63;
        W1s[m * 68 + k] = rW1[idx];
    }
    if (threadIdx.x < 32) {
        b1s[threadIdx.x] = rb1[threadIdx.x];
        W2s[threadIdx.x] = rW2[threadIdx.x];
    }
    __syncthreads();
    float b2 = rb2[0];
    int warp = threadIdx.x >> 5, t = threadIdx.x & 31;
    float* In = InB[warp];
    const float* wp = &W1s[t * 68];
    for (int node = blockIdx.x * 8 + warp; node < n; node += gridDim.x * 8) {
        In[t] = hin[node * 64 + t];
        In[t + 32] = hin[node * 64 + t + 32];
        __syncwarp();
        float acc = b1s[t];
#pragma unroll
        for (int k4 = 0; k4 < 64; k4 += 4) {
            float4 iv = *reinterpret_cast<const float4*>(&In[k4]);
            float4 w = *reinterpret_cast<const float4*>(wp + k4);
            acc += w.x * iv.x + w.y * iv.y + w.z * iv.z + w.w * iv.w;
        }
        __syncwarp();
        acc = fmaxf(acc, 0.f);
        float p = acc * W2s[t];
#pragma unroll
        for (int off = 16; off; off >>= 1) p += __shfl_xor_sync(0xffffffffu, p, off);
        if (t == 0) out[node] = 1.f / (1.f + __expf(-(p + b2)));
    }
}

// ---------------- launch ----------------
extern "C" void kernel_launch(void* const* d_in, const int* in_sizes, int n_in,
                              void* d_out, int out_size) {
    const float* x    = (const float*)d_in[0];
    const int*   ei   = (const int*)d_in[1];
    const float* embW = (const float*)d_in[2];
    const float* embB = (const float*)d_in[3];
    const float* e8W  = (const float*)d_in[4];
    const float* gatW = (const float*)d_in[5];
    const float* attS = (const float*)d_in[6];
    const float* attD = (const float*)d_in[7];
    const float* gatB = (const float*)d_in[8];
    const float* fusW = (const float*)d_in[9];
    const float* fusB = (const float*)d_in[10];
    const float* lnG  = (const float*)d_in[11];
    const float* lnB  = (const float*)d_in[12];
    const float* rW1  = (const float*)d_in[13];
    const float* rb1  = (const float*)d_in[14];
    const float* rW2  = (const float*)d_in[15];
    const float* rb2  = (const float*)d_in[16];
    float* out = (float*)d_out;

    int n = in_sizes[0] / 64;
    int E = in_sizes[1] / 2;
    int n2 = 2 * n;
    int ngrid = 1563;

    void* cnt_addr = nullptr;
    void* tot_addr = nullptr;
    cudaGetSymbolAddress(&cnt_addr, d_cnt);
    cudaGetSymbolAddress(&tot_addr, d_total);
    cudaMemsetAsync(cnt_addr, 0, (size_t)n2 * sizeof(int));
    cudaMemsetAsync(tot_addr, 0, sizeof(int));

    count_kernel<<<(E + 255) / 256, 256>>>(ei, E, n);
    alloc_kernel<<<(n2 + 255) / 256, 256>>>(n2);
    fill_kernel<<<(E + 255) / 256, 256>>>(ei, E, n);
    nodeprep_kernel<<<ngrid + 48, 256>>>(x, embW, embB, gatW, attS, attD, fusW, e8W, ngrid, n);
    layer_kernel<<<ngrid, 256>>>(fusW, fusB, gatB, lnG, lnB, 0, 0, n);
    for (int l = 1; l < 3; l++) {
        int flip = l & 1;
        n1_kernel<<<ngrid, 256>>>(gatW, attS, attD, l, flip, n);
        layer_kernel<<<ngrid, 256>>>(fusW, fusB, gatB, lnG, lnB, l, flip, n);
    }
    readout_kernel<<<ngrid, 256>>>(rW1, rb1, rW2, rb2, out, n);
}

// round 14
// speedup vs baseline: 1.2171x; 1.0381x over previous
#include <cuda_runtime.h>
#include <cuda_fp16.h>

#define MAXN 100000
#define MAXE 1600000

// ---------------- scratch ----------------
__device__ float d_h[MAXN * 64];
__device__ float d_h2[MAXN * 64];
__device__ __half2 d_hh[2][MAXN * 32];  // pre-scaled {dinv*h[t], dinv*h[t+32]}, dbl-buffered
__device__ __half2 d_g2[MAXN * 32];     // {g[t], g[t+32]} per lane
__device__ float2 d_asp[MAXN * 2];      // {as[hA], as[hA+2]} for hA=0,1
__device__ float2 d_adp[MAXN * 2];
__device__ float d_dinv[MAXN];
__device__ float d_Wc[3 * 64 * 64];

__device__ int d_cnt[2 * MAXN];
__device__ int d_off[2 * MAXN];
__device__ int d_cur[2 * MAXN];
__device__ int d_total[1];
__device__ int d_adj[2 * MAXE];

__device__ __forceinline__ float leaky02(float x) { return x > 0.f ? x : 0.2f * x; }

// ---------------- CSR build ----------------
__global__ void count_kernel(const int* __restrict__ ei, int E, int n) {
    int e = blockIdx.x * blockDim.x + threadIdx.x;
    if (e < E) {
        atomicAdd(&d_cnt[ei[e]], 1);
        atomicAdd(&d_cnt[n + ei[E + e]], 1);
    }
}

__global__ void alloc_kernel(int n2) {
    int i = blockIdx.x * blockDim.x + threadIdx.x;
    if (i < n2) {
        int c = d_cnt[i];
        int o = atomicAdd(&d_total[0], c);
        d_off[i] = o;
        d_cur[i] = o;
    }
}

__global__ void fill_kernel(const int* __restrict__ ei, int E, int n) {
    int e = blockIdx.x * blockDim.x + threadIdx.x;
    if (e < E) {
        int r = ei[e], c = ei[E + e];
        int p = atomicAdd(&d_cur[r], 1);
        d_adj[p] = c;
        int p2 = atomicAdd(&d_cur[n + c], 1);
        d_adj[p2] = r;
    }
}

// ---------------- nodeprep: dinv + emb + n1(layer0) + Wc (quad k-chunked GEMVs) ----------------
__global__ void __launch_bounds__(256) nodeprep_kernel(
        const float* __restrict__ x, const float* __restrict__ embW,
        const float* __restrict__ embB, const float* __restrict__ gatW,
        const float* __restrict__ attS, const float* __restrict__ attD,
        const float* __restrict__ fusW, const float* __restrict__ e8W,
        int ngrid, int n) {
    if (blockIdx.x >= (unsigned)ngrid) {
        int bid = blockIdx.x - ngrid;
        int gidx = bid * 256 + threadIdx.x;
        if (gidx < 3 * 4096) {
            int layer = gidx >> 12;
            int idx = gidx & 4095;
            int j = idx >> 6, k = idx & 63;
            const float* F = fusW + layer * 64 * 128;
            const float* Ew = e8W + layer * 64 * 64;
            float acc = 0.f;
#pragma unroll
            for (int m = 0; m < 64; m++) acc += F[j * 128 + m] * Ew[m * 64 + k];
            d_Wc[layer * 4096 + j * 64 + k] = acc;
        }
        return;
    }
    __shared__ float We[64 * 68];   // We[j*68+k] = embW[j][k]
    __shared__ float Wg[64 * 68];   // Wg[j*68+k] = gatW[k][j]
    __shared__ float InB[8][128];   // per-warp: [q*32 + k] for 4 nodes, one 32-k chunk
    __shared__ float bs[64];
    for (int idx = threadIdx.x; idx < 4096; idx += blockDim.x) {
        int j = idx >> 6, k = idx & 63;
        We[j * 68 + k] = embW[idx];
        Wg[k * 68 + j] = gatW[idx];
    }
    if (threadIdx.x < 64) bs[threadIdx.x] = embB[threadIdx.x];
    __syncthreads();
    int warp = threadIdx.x >> 5, t = threadIdx.x & 31;
    float as0 = attS[t], as1 = attS[t + 32];
    float ad0 = attD[t], ad1 = attD[t + 32];
    float* In = InB[warp];
    const float* we0 = &We[t * 68];
    const float* we1 = &We[(t + 32) * 68];
    const float* wg0 = &Wg[t * 68];
    const float* wg1 = &Wg[(t + 32) * 68];
    int gw = blockIdx.x * 8 + warp;
    int totw = ngrid * 8;
    for (int nb = gw * 4; nb < n; nb += totw * 4) {
        float h0q[4], h1q[4];
#pragma unroll
        for (int q = 0; q < 4; q++) { h0q[q] = bs[t]; h1q[q] = bs[t + 32]; }
        // ---- emb quad GEMV, k-chunked ----
#pragma unroll
        for (int c = 0; c < 2; c++) {
#pragma unroll
            for (int q = 0; q < 4; q++) {
                int node = nb + q;
                In[q * 32 + t] = node < n ? x[node * 64 + c * 32 + t] : 0.f;
            }
            __syncwarp();
#pragma unroll
            for (int k4 = 0; k4 < 32; k4 += 4) {
                float4 w0 = *reinterpret_cast<const float4*>(we0 + c * 32 + k4);
                float4 w1 = *reinterpret_cast<const float4*>(we1 + c * 32 + k4);
#pragma unroll
                for (int q = 0; q < 4; q++) {
                    float4 iv = *reinterpret_cast<const float4*>(&In[q * 32 + k4]);
                    h0q[q] += w0.x * iv.x + w0.y * iv.y + w0.z * iv.z + w0.w * iv.w;
                    h1q[q] += w1.x * iv.x + w1.y * iv.y + w1.z * iv.z + w1.w * iv.w;
                }
            }
            __syncwarp();
        }
        // store h, hh, dinv
#pragma unroll
        for (int q = 0; q < 4; q++) {
            int node = nb + q;
            if (node >= n) break;
            float dg = (float)d_cnt[n + node];
            float dvr = dg > 0.f ? rsqrtf(dg) : 0.f;
            if (t == 0) d_dinv[node] = dvr;
            d_h[node * 64 + t] = h0q[q];
            d_h[node * 64 + t + 32] = h1q[q];
            d_hh[0][node * 32 + t] = __floats2half2_rn(dvr * h0q[q], dvr * h1q[q]);
        }
        // ---- gat layer0 quad GEMV, k-chunked (inputs from registers) ----
        float g0q[4] = {0.f, 0.f, 0.f, 0.f}, g1q[4] = {0.f, 0.f, 0.f, 0.f};
#pragma unroll
        for (int c = 0; c < 2; c++) {
#pragma unroll
            for (int q = 0; q < 4; q++) In[q * 32 + t] = c ? h1q[q] : h0q[q];
            __syncwarp();
#pragma unroll
            for (int k4 = 0; k4 < 32; k4 += 4) {
                float4 w0 = *reinterpret_cast<const float4*>(wg0 + c * 32 + k4);
                float4 w1 = *reinterpret_cast<const float4*>(wg1 + c * 32 + k4);
#pragma unroll
                for (int q = 0; q < 4; q++) {
                    float4 iv = *reinterpret_cast<const float4*>(&In[q * 32 + k4]);
                    g0q[q] += w0.x * iv.x + w0.y * iv.y + w0.z * iv.z + w0.w * iv.w;
                    g1q[q] += w1.x * iv.x + w1.y * iv.y + w1.z * iv.z + w1.w * iv.w;
                }
            }
            __syncwarp();
        }
#pragma unroll
        for (int q = 0; q < 4; q++) {
            int node = nb + q;
            if (node >= n) break;
            float g0 = g0q[q], g1 = g1q[q];
            d_g2[node * 32 + t] = __floats2half2_rn(g0, g1);
            float ps0 = g0 * as0, ps1 = g1 * as1;
            float pd0 = g0 * ad0, pd1 = g1 * ad1;
#pragma unroll
            for (int off = 8; off; off >>= 1) {
                ps0 += __shfl_xor_sync(0xffffffffu, ps0, off);
                ps1 += __shfl_xor_sync(0xffffffffu, ps1, off);
                pd0 += __shfl_xor_sync(0xffffffffu, pd0, off);
                pd1 += __shfl_xor_sync(0xffffffffu, pd1, off);
            }
            if ((t & 15) == 0) {
                int hh = t >> 4;
                d_asp[node * 2 + hh] = make_float2(ps0, ps1);
                d_adp[node * 2 + hh] = make_float2(pd0, pd1);
            }
        }
    }
}

// ---------------- N1 (layers 1,2): quad k-chunked GEMV ----------------
__global__ void __launch_bounds__(256) n1_kernel(
        const float* __restrict__ gatW, const float* __restrict__ attS,
        const float* __restrict__ attD, int layer, int flip, int n) {
    const float* hin = flip ? d_h2 : d_h;
    __shared__ float Wn[64 * 68];
    __shared__ float InB[8][128];
    const float* W = gatW + layer * 4096;
    for (int idx = threadIdx.x; idx < 4096; idx += blockDim.x) {
        int k = idx >> 6, j = idx & 63;
        Wn[j * 68 + k] = W[idx];
    }
    __syncthreads();
    int warp = threadIdx.x >> 5, t = threadIdx.x & 31;
    float as0 = attS[layer * 64 + t], as1 = attS[layer * 64 + t + 32];
    float ad0 = attD[layer * 64 + t], ad1 = attD[layer * 64 + t + 32];
    float* In = InB[warp];
    const float* w0p = &Wn[t * 68];
    const float* w1p = &Wn[(t + 32) * 68];
    int gw = blockIdx.x * 8 + warp;
    int totw = gridDim.x * 8;
    for (int nb = gw * 4; nb < n; nb += totw * 4) {
        float g0q[4] = {0.f, 0.f, 0.f, 0.f}, g1q[4] = {0.f, 0.f, 0.f, 0.f};
#pragma unroll
        for (int c = 0; c < 2; c++) {
#pragma unroll
            for (int q = 0; q < 4; q++) {
                int node = nb + q;
                In[q * 32 + t] = node < n ? hin[node * 64 + c * 32 + t] : 0.f;
            }
            __syncwarp();
#pragma unroll
            for (int k4 = 0; k4 < 32; k4 += 4) {
                float4 w0 = *reinterpret_cast<const float4*>(w0p + c * 32 + k4);
                float4 w1 = *reinterpret_cast<const float4*>(w1p + c * 32 + k4);
#pragma unroll
                for (int q = 0; q < 4; q++) {
                    float4 iv = *reinterpret_cast<const float4*>(&In[q * 32 + k4]);
                    g0q[q] += w0.x * iv.x + w0.y * iv.y + w0.z * iv.z + w0.w * iv.w;
                    g1q[q] += w1.x * iv.x + w1.y * iv.y + w1.z * iv.z + w1.w * iv.w;
                }
            }
            __syncwarp();
        }
#pragma unroll
        for (int q = 0; q < 4; q++) {
            int node = nb + q;
            if (node >= n) break;
            float g0 = g0q[q], g1 = g1q[q];
            d_g2[node * 32 + t] = __floats2half2_rn(g0, g1);
            float ps0 = g0 * as0, ps1 = g1 * as1;
            float pd0 = g0 * ad0, pd1 = g1 * ad1;
#pragma unroll
            for (int off = 8; off; off >>= 1) {
                ps0 += __shfl_xor_sync(0xffffffffu, ps0, off);
                ps1 += __shfl_xor_sync(0xffffffffu, ps1, off);
                pd0 += __shfl_xor_sync(0xffffffffu, pd0, off);
                pd1 += __shfl_xor_sync(0xffffffffu, pd1, off);
            }
            if ((t & 15) == 0) {
                int hh = t >> 4;
                d_asp[node * 2 + hh] = make_float2(ps0, ps1);
                d_adp[node * 2 + hh] = make_float2(pd0, pd1);
            }
        }
    }
}

// ---------------- layer: R13 form (pair gathers + pair GEMV) ----------------
__global__ void __launch_bounds__(256) layer_kernel(
        const float* __restrict__ fusW, const float* __restrict__ fusB,
        const float* __restrict__ gatB, const float* __restrict__ lnG,
        const float* __restrict__ lnB, int layer, int flip, int n) {
    const float* hin = flip ? d_h2 : d_h;
    float* hout = flip ? d_h : d_h2;
    const __half2* hhin = d_hh[flip];
    __half2* hhout = d_hh[flip ^ 1];
    __shared__ float Wst[64 * 132];
    __shared__ float InB[8][256];
    __shared__ float fb[64], gb[64], lg[64], lb[64];
    const float* Wc = d_Wc + layer * 4096;
    const float* F = fusW + layer * 64 * 128;
    for (int idx = threadIdx.x; idx < 8192; idx += 256) {
        int j = idx >> 7, k = idx & 127;
        Wst[j * 132 + k] = (k < 64) ? Wc[j * 64 + k] : F[j * 128 + 64 + (k - 64)];
    }
    if (threadIdx.x < 64) {
        fb[threadIdx.x] = fusB[layer * 64 + threadIdx.x];
        gb[threadIdx.x] = gatB[layer * 64 + threadIdx.x];
        lg[threadIdx.x] = lnG[layer * 64 + threadIdx.x];
        lb[threadIdx.x] = lnB[layer * 64 + threadIdx.x];
    }
    __syncthreads();
    int warp = threadIdx.x >> 5, t = threadIdx.x & 31;
    int hA = t >> 4;
    int gw = blockIdx.x * 8 + warp;
    int totw = gridDim.x * 8;
    float* In = InB[warp];
    const float* w0p = &Wst[t * 132];
    const float* w1p = &Wst[(t + 32) * 132];

    for (int nb = gw * 2; nb < n; nb += totw * 2) {
#pragma unroll
        for (int q = 0; q < 2; q++) {
            int node = nb + q;
            float a0 = 0.f, a1 = 0.f, xx0 = 0.f, xx1 = 0.f;
            if (node < n) {
                float2 adv = d_adp[node * 2 + hA];
                float2 asn = d_asp[node * 2 + hA];
                float eeS0 = __expf(leaky02(asn.x + adv.x));
                float eeS1 = __expf(leaky02(asn.y + adv.y));
                float2 gself = __half22float2(d_g2[node * 32 + t]);
                float w0 = eeS0 * gself.x, w1 = eeS1 * gself.y;
                float s0 = eeS0, s1 = eeS1;
                int beg = d_off[n + node];
                int dc = d_cnt[n + node];
                for (int i = 0; i < dc; i++) {
                    int src = __ldg(&d_adj[beg + i]);
                    float2 gv = __half22float2(d_g2[src * 32 + t]);
                    float2 asv = __ldg(&d_asp[src * 2 + hA]);
                    float ee0 = __expf(leaky02(asv.x + adv.x));
                    float ee1 = __expf(leaky02(asv.y + adv.y));
                    w0 += ee0 * gv.x;
                    w1 += ee1 * gv.y;
                    s0 += ee0;
                    s1 += ee1;
                }
                xx0 = w0 / s0 + gb[t];
                xx1 = w1 / s1 + gb[t + 32];
                float e0 = 0.f, e1 = 0.f;
                int beg2 = d_off[node];
                int dr = d_cnt[node];
                for (int i = 0; i < dr; i++) {
                    int c = __ldg(&d_adj[beg2 + i]);
                    float2 hv = __half22float2(hhin[c * 32 + t]);
                    e0 += hv.x;
                    e1 += hv.y;
                }
                float dvr = d_dinv[node];
                a0 = e0 * dvr;
                a1 = e1 * dvr;
            }
            In[q * 128 + t] = a0;
            In[q * 128 + t + 32] = a1;
            In[q * 128 + t + 64] = xx0;
            In[q * 128 + t + 96] = xx1;
        }
        __syncwarp();

        float accA0 = fb[t], accA1 = fb[t + 32];
        float accB0 = fb[t], accB1 = fb[t + 32];
#pragma unroll 8
        for (int k4 = 0; k4 < 128; k4 += 4) {
            float4 w0 = *reinterpret_cast<const float4*>(w0p + k4);
            float4 w1 = *reinterpret_cast<const float4*>(w1p + k4);
            float4 ia = *reinterpret_cast<const float4*>(&In[k4]);
            float4 ib = *reinterpret_cast<const float4*>(&In[128 + k4]);
            accA0 += w0.x * ia.x + w0.y * ia.y + w0.z * ia.z + w0.w * ia.w;
            accA1 += w1.x * ia.x + w1.y * ia.y + w1.z * ia.z + w1.w * ia.w;
            accB0 += w0.x * ib.x + w0.y * ib.y + w0.z * ib.z + w0.w * ib.w;
            accB1 += w1.x * ib.x + w1.y * ib.y + w1.z * ib.z + w1.w * ib.w;
        }
        __syncwarp();

#pragma unroll
        for (int q = 0; q < 2; q++) {
            int node = nb + q;
            if (node >= n) break;
            float c0 = (q == 0 ? accA0 : accB0) + hin[node * 64 + t];
            float c1 = (q == 0 ? accA1 : accB1) + hin[node * 64 + t + 32];
            float ssum = c0 + c1;
#pragma unroll
            for (int off = 16; off; off >>= 1) ssum += __shfl_xor_sync(0xffffffffu, ssum, off);
            float mu = ssum * (1.f / 64.f);
            float dd0 = c0 - mu, dd1 = c1 - mu;
            float vs = dd0 * dd0 + dd1 * dd1;
#pragma unroll
            for (int off = 16; off; off >>= 1) vs += __shfl_xor_sync(0xffffffffu, vs, off);
            float rstd = rsqrtf(vs * (1.f / 64.f) + 1e-5f);
            float o0 = fmaxf(dd0 * rstd * lg[t] + lb[t], 0.f);
            float o1 = fmaxf(dd1 * rstd * lg[t + 32] + lb[t + 32], 0.f);
            hout[node * 64 + t] = o0;
            hout[node * 64 + t + 32] = o1;
            float dvr = d_dinv[node];
            hhout[node * 32 + t] = __floats2half2_rn(dvr * o0, dvr * o1);
        }
    }
}

// ---------------- readout ----------------
__global__ void readout_kernel(const float* __restrict__ rW1, const float* __restrict__ rb1,
                               const float* __restrict__ rW2, const float* __restrict__ rb2,
                               float* __restrict__ out, int n) {
    const float* hin = d_h2;
    __shared__ float W1s[32 * 68];
    __shared__ float InB[8][64];
    __shared__ float b1s[32], W2s[32];
    for (int idx = threadIdx.x; idx < 2048; idx += blockDim.x) {
        int m = idx >> 6, k = idx & 63;
        W1s[m * 68 + k] = rW1[idx];
    }
    if (threadIdx.x < 32) {
        b1s[threadIdx.x] = rb1[threadIdx.x];
        W2s[threadIdx.x] = rW2[threadIdx.x];
    }
    __syncthreads();
    float b2 = rb2[0];
    int warp = threadIdx.x >> 5, t = threadIdx.x & 31;
    float* In = InB[warp];
    const float* wp = &W1s[t * 68];
    for (int node = blockIdx.x * 8 + warp; node < n; node += gridDim.x * 8) {
        In[t] = hin[node * 64 + t];
        In[t + 32] = hin[node * 64 + t + 32];
        __syncwarp();
        float acc = b1s[t];
#pragma unroll
        for (int k4 = 0; k4 < 64; k4 += 4) {
            float4 iv = *reinterpret_cast<const float4*>(&In[k4]);
            float4 w = *reinterpret_cast<const float4*>(wp + k4);
            acc += w.x * iv.x + w.y * iv.y + w.z * iv.z + w.w * iv.w;
        }
        __syncwarp();
        acc = fmaxf(acc, 0.f);
        float p = acc * W2s[t];
#pragma unroll
        for (int off = 16; off; off >>= 1) p += __shfl_xor_sync(0xffffffffu, p, off);
        if (t == 0) out[node] = 1.f / (1.f + __expf(-(p + b2)));
    }
}

// ---------------- launch ----------------
extern "C" void kernel_launch(void* const* d_in, const int* in_sizes, int n_in,
                              void* d_out, int out_size) {
    const float* x    = (const float*)d_in[0];
    const int*   ei   = (const int*)d_in[1];
    const float* embW = (const float*)d_in[2];
    const float* embB = (const float*)d_in[3];
    const float* e8W  = (const float*)d_in[4];
    const float* gatW = (const float*)d_in[5];
    const float* attS = (const float*)d_in[6];
    const float* attD = (const float*)d_in[7];
    const float* gatB = (const float*)d_in[8];
    const float* fusW = (const float*)d_in[9];
    const float* fusB = (const float*)d_in[10];
    const float* lnG  = (const float*)d_in[11];
    const float* lnB  = (const float*)d_in[12];
    const float* rW1  = (const float*)d_in[13];
    const float* rb1  = (const float*)d_in[14];
    const float* rW2  = (const float*)d_in[15];
    const float* rb2  = (const float*)d_in[16];
    float* out = (float*)d_out;

    int n = in_sizes[0] / 64;
    int E = in_sizes[1] / 2;
    int n2 = 2 * n;
    int ngrid = 1563;

    void* cnt_addr = nullptr;
    void* tot_addr = nullptr;
    cudaGetSymbolAddress(&cnt_addr, d_cnt);
    cudaGetSymbolAddress(&tot_addr, d_total);
    cudaMemsetAsync(cnt_addr, 0, (size_t)n2 * sizeof(int));
    cudaMemsetAsync(tot_addr, 0, sizeof(int));

    count_kernel<<<(E + 255) / 256, 256>>>(ei, E, n);
    alloc_kernel<<<(n2 + 255) / 256, 256>>>(n2);
    fill_kernel<<<(E + 255) / 256, 256>>>(ei, E, n);
    nodeprep_kernel<<<ngrid + 48, 256>>>(x, embW, embB, gatW, attS, attD, fusW, e8W, ngrid, n);
    layer_kernel<<<ngrid, 256>>>(fusW, fusB, gatB, lnG, lnB, 0, 0, n);
    for (int l = 1; l < 3; l++) {
        int flip = l & 1;
        n1_kernel<<<ngrid, 256>>>(gatW, attS, attD, l, flip, n);
        layer_kernel<<<ngrid, 256>>>(fusW, fusB, gatB, lnG, lnB, l, flip, n);
    }
    readout_kernel<<<ngrid, 256>>>(rW1, rb1, rW2, rb2, out, n);
}